// round 1
// baseline (speedup 1.0000x reference)
#include <cuda_runtime.h>
#include <math.h>

// ---------------------------------------------------------------------------
// EnhancedSNNCifar: T=8 SNN forward, fp32 throughout.
// Pipeline: conv1(128 imgs, shared across T) -> BN -> LIF -> conv2..6 over
// T*N=1024 imgs with BN(training stats)+LIF, maxpools, fc1+LIF, fc2+LIF, mean.
// All reductions are deterministic (fixed-order two-stage, double precision).
// ---------------------------------------------------------------------------

#define TSTEPS 8

// scratch (device globals; no allocations allowed)
__device__ float  g_y [33554432];   // conv pre-activations (max 1024*32*32*32)
__device__ float  g_s [33554432];   // spikes
__device__ float  g_sp[ 8388608];   // pooled spikes (max 1024*32*16*16)
__device__ float  g_fc1 [131072];   // fc1 pre-act [1024,128]
__device__ float  g_fc1s[131072];   // fc1 spikes
__device__ float  g_fc2 [ 10240];   // fc2 pre-act [1024,10]
__device__ double g_ps [128 * 64];  // BN partial sums
__device__ double g_ps2[128 * 64];  // BN partial sum-of-squares
__device__ float  g_inv  [128];
__device__ float  g_shift[128];

// ---------------------------------------------------------------------------
// Direct 3x3 conv, pad=1, stride=1.  Each thread: 2x2 output pixels x 8 couts.
// Block = 256 threads covers 1024 pixels = IMGS images of H*W each.
// grid.x = M/IMGS image groups, grid.y = COUT/8 cout groups.
// ---------------------------------------------------------------------------
template<int CIN, int COUT, int H, int W, int IMGS>
__global__ __launch_bounds__(256)
void conv3x3_kernel(const float* __restrict__ in, const float* __restrict__ wt,
                    const float* __restrict__ bias, float* __restrict__ out)
{
    constexpr int QPI = (H / 2) * (W / 2);     // quads per image
    static_assert(IMGS * QPI == 256, "block mapping");
    constexpr int PW = W + 2, PH = H + 2;
    constexpr int IN_TILE = PH * PW;

    __shared__ float s_in[IMGS * IN_TILE];
    __shared__ float s_w[CIN * 72];            // [c][8 couts][9 taps]

    const int tid = threadIdx.x;
    const int cog = blockIdx.y;
    const int m0  = blockIdx.x * IMGS;

    // stage weights for this block's 8 couts (all input channels)
    for (int i = tid; i < CIN * 72; i += 256) {
        int c = i / 72, r = i % 72, j = r / 9, k = r % 9;
        s_w[i] = wt[((size_t)(cog * 8 + j) * CIN + c) * 9 + k];
    }

    const int img_l = tid / QPI;
    const int q     = tid % QPI;
    const int qy = q / (W / 2), qx = q % (W / 2);
    const int oy = qy * 2, ox = qx * 2;

    float acc[4][8];
#pragma unroll
    for (int p = 0; p < 4; p++)
#pragma unroll
        for (int j = 0; j < 8; j++) acc[p][j] = 0.f;

    float bj[8];
#pragma unroll
    for (int j = 0; j < 8; j++) bj[j] = bias[cog * 8 + j];

#pragma unroll 1
    for (int c = 0; c < CIN; ++c) {
        __syncthreads();
        // stage input tiles (with zero halo) for IMGS images, channel c
        for (int i = tid; i < IMGS * IN_TILE; i += 256) {
            int il = i / IN_TILE, r = i % IN_TILE;
            int py = r / PW, px = r % PW;
            int iy = py - 1, ix = px - 1;
            float v = 0.f;
            if (iy >= 0 && iy < H && ix >= 0 && ix < W)
                v = in[((size_t)(m0 + il) * CIN + c) * (H * W) + iy * W + ix];
            s_in[i] = v;
        }
        __syncthreads();

        // 4x4 input window for this thread's 2x2 output quad
        float xv[4][4];
        const float* sb = &s_in[img_l * IN_TILE];
#pragma unroll
        for (int dy = 0; dy < 4; dy++)
#pragma unroll
            for (int dx = 0; dx < 4; dx++)
                xv[dy][dx] = sb[(oy + dy) * PW + (ox + dx)];

        const float* wc = &s_w[c * 72];
#pragma unroll
        for (int ky = 0; ky < 3; ky++)
#pragma unroll
            for (int kx = 0; kx < 3; kx++) {
                float w8[8];
#pragma unroll
                for (int j = 0; j < 8; j++) w8[j] = wc[j * 9 + ky * 3 + kx];
#pragma unroll
                for (int py = 0; py < 2; py++)
#pragma unroll
                    for (int px = 0; px < 2; px++) {
                        float xvv = xv[py + ky][px + kx];
#pragma unroll
                        for (int j = 0; j < 8; j++)
                            acc[py * 2 + px][j] = fmaf(xvv, w8[j], acc[py * 2 + px][j]);
                    }
            }
    }

#pragma unroll
    for (int j = 0; j < 8; j++) {
        int co = cog * 8 + j;
        size_t base = ((size_t)(m0 + img_l) * COUT + co) * (H * W);
#pragma unroll
        for (int py = 0; py < 2; py++)
#pragma unroll
            for (int px = 0; px < 2; px++)
                out[base + (oy + py) * W + (ox + px)] = acc[py * 2 + px][j] + bj[j];
    }
}

// ---------------------------------------------------------------------------
// BN stats: deterministic two-stage reduction in double.
// grid (C, 64), block 256.
// ---------------------------------------------------------------------------
__global__ void bn_stats_kernel(const float* __restrict__ y, int C, int HW, int M)
{
    const int c = blockIdx.x, b = blockIdx.y;
    const long total = (long)M * HW;
    const long chunk = (total + 63) / 64;
    long beg = (long)b * chunk;
    long end = beg + chunk; if (end > total) end = total;

    double s = 0.0, s2 = 0.0;
    for (long e = beg + threadIdx.x; e < end; e += 256) {
        long m = e / HW, hw = e % HW;
        double v = (double)y[((size_t)m * C + c) * HW + hw];
        s += v; s2 += v * v;
    }
    __shared__ double ss[256], ss2[256];
    ss[threadIdx.x] = s; ss2[threadIdx.x] = s2;
    __syncthreads();
    for (int st = 128; st > 0; st >>= 1) {
        if (threadIdx.x < st) {
            ss[threadIdx.x]  += ss[threadIdx.x + st];
            ss2[threadIdx.x] += ss2[threadIdx.x + st];
        }
        __syncthreads();
    }
    if (threadIdx.x == 0) {
        g_ps [c * 64 + b] = ss[0];
        g_ps2[c * 64 + b] = ss2[0];
    }
}

__global__ void bn_finalize_kernel(const float* __restrict__ g,
                                   const float* __restrict__ be, int C, double n)
{
    int c = threadIdx.x;
    if (c >= C) return;
    double s = 0.0, s2 = 0.0;
    for (int b = 0; b < 64; b++) { s += g_ps[c * 64 + b]; s2 += g_ps2[c * 64 + b]; }
    double mean = s / n;
    double var  = s2 / n - mean * mean;
    float invf = g[c] / sqrtf((float)var + 1e-5f);
    g_inv[c]   = invf;
    g_shift[c] = be[c] - (float)mean * invf;
}

// ---------------------------------------------------------------------------
// BN apply + LIF scan over T.  Sites = 128 * C * HW, y layout [(t*128+n),C,HW]
// (tstride=0 for layer 1: same pre-act each timestep).
// ---------------------------------------------------------------------------
__global__ void bn_lif_kernel(const float* __restrict__ y, float* __restrict__ s,
                              int C, int HW, long tstride)
{
    const int sites = 128 * C * HW;
    const int idx = blockIdx.x * 256 + threadIdx.x;
    if (idx >= sites) return;
    const int c = (idx / HW) % C;
    const float vi = g_inv[c], sh = g_shift[c];
    float v = 0.f;
    const size_t ss = (size_t)sites;
#pragma unroll
    for (int t = 0; t < TSTEPS; t++) {
        float x = fmaf(y[(size_t)t * tstride + idx], vi, sh);
        v = v + (x - v) * 0.5f;          // v += (x - v)/TAU, TAU=2
        float spike = (v >= 1.0f) ? 1.0f : 0.0f;
        s[ss * t + idx] = spike;
        if (v >= 1.0f) v = 0.0f;         // hard reset
    }
}

// 2x2 maxpool on [1024, C, H, W]
__global__ void pool_kernel(const float* __restrict__ in, float* __restrict__ out,
                            int C, int H, int W)
{
    const int OW = W / 2, OH = H / 2;
    const int total = 1024 * C * OH * OW;
    const int idx = blockIdx.x * 256 + threadIdx.x;
    if (idx >= total) return;
    const int ohw = OH * OW;
    const int mc = idx / ohw, r = idx % ohw;
    const int oy = r / OW, ox = r % OW;
    const float* p = in + (size_t)mc * H * W + (2 * oy) * W + 2 * ox;
    out[idx] = fmaxf(fmaxf(p[0], p[1]), fmaxf(p[W], p[W + 1]));
}

// fc1: [1024,2048] x [128,2048]^T ; one row per block, one out-feature/thread
__global__ __launch_bounds__(128)
void fc1_kernel(const float* __restrict__ in, const float* __restrict__ w,
                const float* __restrict__ b, float* __restrict__ out)
{
    __shared__ float s_in[2048];
    const int r = blockIdx.x;
    for (int i = threadIdx.x; i < 2048; i += 128) s_in[i] = in[(size_t)r * 2048 + i];
    __syncthreads();
    const int o = threadIdx.x;
    const float* wr = w + (size_t)o * 2048;
    float a0 = 0.f, a1 = 0.f, a2 = 0.f, a3 = 0.f;
    for (int f = 0; f < 2048; f += 4) {
        a0 = fmaf(s_in[f],     wr[f],     a0);
        a1 = fmaf(s_in[f + 1], wr[f + 1], a1);
        a2 = fmaf(s_in[f + 2], wr[f + 2], a2);
        a3 = fmaf(s_in[f + 3], wr[f + 3], a3);
    }
    out[(size_t)r * 128 + o] = ((a0 + a1) + (a2 + a3)) + b[o];
}

// fc2: [1024,128] x [10,128]^T
__global__ void fc2_kernel(const float* __restrict__ in, const float* __restrict__ w,
                           const float* __restrict__ b, float* __restrict__ out)
{
    const int idx = blockIdx.x * 256 + threadIdx.x;
    if (idx >= 10240) return;
    const int r = idx / 10, o = idx % 10;
    const float* ir = in + (size_t)r * 128;
    const float* wr = w + (size_t)o * 128;
    float a = 0.f;
#pragma unroll 4
    for (int f = 0; f < 128; f++) a = fmaf(ir[f], wr[f], a);
    out[idx] = a + b[o];
}

__global__ void lif_kernel(const float* __restrict__ y, float* __restrict__ s, int sites)
{
    const int idx = blockIdx.x * 256 + threadIdx.x;
    if (idx >= sites) return;
    float v = 0.f;
#pragma unroll
    for (int t = 0; t < TSTEPS; t++) {
        float x = y[(size_t)t * sites + idx];
        v = v + (x - v) * 0.5f;
        float spike = (v >= 1.0f) ? 1.0f : 0.0f;
        s[(size_t)t * sites + idx] = spike;
        if (v >= 1.0f) v = 0.0f;
    }
}

__global__ void lif_mean_kernel(const float* __restrict__ y, float* __restrict__ out,
                                int sites)
{
    const int idx = blockIdx.x * 256 + threadIdx.x;
    if (idx >= sites) return;
    float v = 0.f, cnt = 0.f;
#pragma unroll
    for (int t = 0; t < TSTEPS; t++) {
        float x = y[(size_t)t * sites + idx];
        v = v + (x - v) * 0.5f;
        if (v >= 1.0f) { cnt += 1.0f; v = 0.0f; }
    }
    out[idx] = cnt * 0.125f;
}

// ---------------------------------------------------------------------------
extern "C" void kernel_launch(void* const* d_in, const int* in_sizes, int n_in,
                              void* d_out, int out_size)
{
    const float* x     = (const float*)d_in[0];
    const float* w[7];  const float* bb[7];  const float* gg[7];  const float* be[7];
    for (int L = 1; L <= 6; L++) {
        w [L] = (const float*)d_in[1 + 4 * (L - 1) + 0];
        bb[L] = (const float*)d_in[1 + 4 * (L - 1) + 1];
        gg[L] = (const float*)d_in[1 + 4 * (L - 1) + 2];
        be[L] = (const float*)d_in[1 + 4 * (L - 1) + 3];
    }
    const float* fc1_w = (const float*)d_in[25];
    const float* fc1_b = (const float*)d_in[26];
    const float* fc2_w = (const float*)d_in[27];
    const float* fc2_b = (const float*)d_in[28];
    float* out = (float*)d_out;

    float *y, *s, *sp, *f1, *f1s, *f2;
    cudaGetSymbolAddress((void**)&y,   g_y);
    cudaGetSymbolAddress((void**)&s,   g_s);
    cudaGetSymbolAddress((void**)&sp,  g_sp);
    cudaGetSymbolAddress((void**)&f1,  g_fc1);
    cudaGetSymbolAddress((void**)&f1s, g_fc1s);
    cudaGetSymbolAddress((void**)&f2,  g_fc2);

    // ---- Layer 1 (input identical across T: conv over 128 imgs only) ----
    conv3x3_kernel<3, 32, 32, 32, 1><<<dim3(128, 4), 256>>>(x, w[1], bb[1], y);
    bn_stats_kernel<<<dim3(32, 64), 256>>>(y, 32, 1024, 128);
    bn_finalize_kernel<<<1, 128>>>(gg[1], be[1], 32, 128.0 * 1024.0);
    bn_lif_kernel<<<16384, 256>>>(y, s, 32, 1024, 0);

    // ---- Layer 2 ----
    conv3x3_kernel<32, 32, 32, 32, 1><<<dim3(1024, 4), 256>>>(s, w[2], bb[2], y);
    bn_stats_kernel<<<dim3(32, 64), 256>>>(y, 32, 1024, 1024);
    bn_finalize_kernel<<<1, 128>>>(gg[2], be[2], 32, 1024.0 * 1024.0);
    bn_lif_kernel<<<16384, 256>>>(y, s, 32, 1024, (long)128 * 32 * 1024);
    pool_kernel<<<(1024 * 32 * 256 + 255) / 256, 256>>>(s, sp, 32, 32, 32);

    // ---- Layer 3 ----
    conv3x3_kernel<32, 64, 16, 16, 4><<<dim3(256, 8), 256>>>(sp, w[3], bb[3], y);
    bn_stats_kernel<<<dim3(64, 64), 256>>>(y, 64, 256, 1024);
    bn_finalize_kernel<<<1, 128>>>(gg[3], be[3], 64, 1024.0 * 256.0);
    bn_lif_kernel<<<8192, 256>>>(y, s, 64, 256, (long)128 * 64 * 256);

    // ---- Layer 4 ----
    conv3x3_kernel<64, 64, 16, 16, 4><<<dim3(256, 8), 256>>>(s, w[4], bb[4], y);
    bn_stats_kernel<<<dim3(64, 64), 256>>>(y, 64, 256, 1024);
    bn_finalize_kernel<<<1, 128>>>(gg[4], be[4], 64, 1024.0 * 256.0);
    bn_lif_kernel<<<8192, 256>>>(y, s, 64, 256, (long)128 * 64 * 256);
    pool_kernel<<<(1024 * 64 * 64 + 255) / 256, 256>>>(s, sp, 64, 16, 16);

    // ---- Layer 5 ----
    conv3x3_kernel<64, 128, 8, 8, 16><<<dim3(64, 16), 256>>>(sp, w[5], bb[5], y);
    bn_stats_kernel<<<dim3(128, 64), 256>>>(y, 128, 64, 1024);
    bn_finalize_kernel<<<1, 128>>>(gg[5], be[5], 128, 1024.0 * 64.0);
    bn_lif_kernel<<<4096, 256>>>(y, s, 128, 64, (long)128 * 128 * 64);

    // ---- Layer 6 ----
    conv3x3_kernel<128, 128, 8, 8, 16><<<dim3(64, 16), 256>>>(s, w[6], bb[6], y);
    bn_stats_kernel<<<dim3(128, 64), 256>>>(y, 128, 64, 1024);
    bn_finalize_kernel<<<1, 128>>>(gg[6], be[6], 128, 1024.0 * 64.0);
    bn_lif_kernel<<<4096, 256>>>(y, s, 128, 64, (long)128 * 128 * 64);
    pool_kernel<<<(1024 * 128 * 16 + 255) / 256, 256>>>(s, sp, 128, 8, 8);

    // ---- FC head ----
    fc1_kernel<<<1024, 128>>>(sp, fc1_w, fc1_b, f1);
    lif_kernel<<<(16384 + 255) / 256, 256>>>(f1, f1s, 16384);
    fc2_kernel<<<40, 256>>>(f1s, fc2_w, fc2_b, f2);
    lif_mean_kernel<<<5, 256>>>(f2, out, 1280);
}

// round 2
// speedup vs baseline: 1.3423x; 1.3423x over previous
#include <cuda_runtime.h>
#include <math.h>

// ---------------------------------------------------------------------------
// EnhancedSNNCifar: T=8 SNN forward, fp32 throughout.
// R1: vectorized conv inner loop (LDS.64/LDS.128), 4-channel staging chunks,
//     BN+LIF+maxpool fusion (layers 2/4/6), fc1 row blocking.
// ---------------------------------------------------------------------------

#define TSTEPS 8

// scratch (device globals; no allocations allowed)
__device__ float  g_y [33554432];   // conv pre-activations (max 1024*32*32*32)
__device__ float  g_s [33554432];   // spikes
__device__ float  g_sp[ 8388608];   // pooled spikes
__device__ float  g_fc1 [131072];   // fc1 pre-act [1024,128]
__device__ float  g_fc1s[131072];   // fc1 spikes
__device__ float  g_fc2 [ 10240];   // fc2 pre-act [1024,10]
__device__ double g_ps [128 * 64];  // BN partial sums
__device__ double g_ps2[128 * 64];  // BN partial sum-of-squares
__device__ float  g_inv  [128];
__device__ float  g_shift[128];

// ---------------------------------------------------------------------------
// Direct 3x3 conv, pad=1, stride=1.  Thread: 2x2 pixels x 8 couts.
// Block = 256 threads = IMGS images * QPI quads.  CH input channels staged
// per sync round; weights in smem as [c][tap][8 couts] for LDS.128.
// ---------------------------------------------------------------------------
template<int CIN, int COUT, int H, int W, int IMGS, int CH>
__global__ __launch_bounds__(256)
void conv3x3_kernel(const float* __restrict__ in, const float* __restrict__ wt,
                    const float* __restrict__ bias, float* __restrict__ out)
{
    constexpr int QPI = (H / 2) * (W / 2);
    static_assert(IMGS * QPI == 256, "block mapping");
    constexpr int PW = W + 2, PH = H + 2;
    constexpr int IN_TILE = PH * PW;

    __shared__ float s_in[CH][IMGS * IN_TILE];
    __shared__ __align__(16) float s_w[CH][9][8];

    const int tid = threadIdx.x;
    const int cog = blockIdx.y;
    const int m0  = blockIdx.x * IMGS;

    const int img_l = tid / QPI;
    const int q     = tid % QPI;
    const int qy = q / (W / 2), qx = q % (W / 2);
    const int oy = qy * 2, ox = qx * 2;

    float acc[4][8];
#pragma unroll
    for (int p = 0; p < 4; p++)
#pragma unroll
        for (int j = 0; j < 8; j++) acc[p][j] = 0.f;

#pragma unroll 1
    for (int c0 = 0; c0 < CIN; c0 += CH) {
        __syncthreads();
        // stage weights: CH channels x 8 couts x 9 taps, layout [c][tap][cout]
        for (int i = tid; i < CH * 72; i += 256) {
            int c = i / 72, r = i % 72, j = r / 9, k = r % 9;
            s_w[c][k][j] = wt[((size_t)(cog * 8 + j) * CIN + (c0 + c)) * 9 + k];
        }
        // stage input tiles with zero halo for CH channels
        for (int i = tid; i < CH * IMGS * IN_TILE; i += 256) {
            int c = i / (IMGS * IN_TILE), r = i % (IMGS * IN_TILE);
            int il = r / IN_TILE, rr = r % IN_TILE;
            int py = rr / PW, px = rr % PW;
            int iy = py - 1, ix = px - 1;
            float v = 0.f;
            if (iy >= 0 && iy < H && ix >= 0 && ix < W)
                v = in[((size_t)(m0 + il) * CIN + (c0 + c)) * (H * W) + iy * W + ix];
            s_in[c][r] = v;
        }
        __syncthreads();

#pragma unroll 1
        for (int c = 0; c < CH; ++c) {
            // 4x4 input window via aligned float2 loads (ox even, PW even)
            float xv[4][4];
            const float* sb = &s_in[c][img_l * IN_TILE + oy * PW + ox];
#pragma unroll
            for (int dy = 0; dy < 4; dy++) {
                float2 a = *(const float2*)(sb + dy * PW);
                float2 b = *(const float2*)(sb + dy * PW + 2);
                xv[dy][0] = a.x; xv[dy][1] = a.y; xv[dy][2] = b.x; xv[dy][3] = b.y;
            }
#pragma unroll
            for (int k = 0; k < 9; k++) {
                const int ky = k / 3, kx = k % 3;
                float4 wlo = *(const float4*)&s_w[c][k][0];
                float4 whi = *(const float4*)&s_w[c][k][4];
                float w8[8] = {wlo.x, wlo.y, wlo.z, wlo.w, whi.x, whi.y, whi.z, whi.w};
#pragma unroll
                for (int py = 0; py < 2; py++)
#pragma unroll
                    for (int px = 0; px < 2; px++) {
                        const float xvv = xv[py + ky][px + kx];
#pragma unroll
                        for (int j = 0; j < 8; j++)
                            acc[py * 2 + px][j] = fmaf(xvv, w8[j], acc[py * 2 + px][j]);
                    }
            }
        }
    }

    float bj[8];
#pragma unroll
    for (int j = 0; j < 8; j++) bj[j] = bias[cog * 8 + j];

#pragma unroll
    for (int j = 0; j < 8; j++) {
        const int co = cog * 8 + j;
        const size_t base = ((size_t)(m0 + img_l) * COUT + co) * (H * W);
#pragma unroll
        for (int py = 0; py < 2; py++) {
            float2 v2 = make_float2(acc[py * 2 + 0][j] + bj[j], acc[py * 2 + 1][j] + bj[j]);
            *(float2*)&out[base + (oy + py) * W + ox] = v2;
        }
    }
}

// ---------------------------------------------------------------------------
// BN stats: deterministic two-stage reduction in double, float4 loads.
// grid (C, 64), block 256.  HW4 = HW/4.
// ---------------------------------------------------------------------------
__global__ void bn_stats_kernel(const float* __restrict__ y, int C, int HW4, int M)
{
    const int c = blockIdx.x, b = blockIdx.y;
    const long total4 = (long)M * HW4;
    const long chunk = (total4 + 63) / 64;
    long beg = (long)b * chunk;
    long end = beg + chunk; if (end > total4) end = total4;

    const float4* y4 = (const float4*)y;
    double s = 0.0, s2 = 0.0;
    for (long e = beg + threadIdx.x; e < end; e += 256) {
        long m = e / HW4; int off = (int)(e % HW4);
        float4 v = y4[((size_t)m * C + c) * HW4 + off];
        double a = v.x, bb = v.y, cc = v.z, dd = v.w;
        s += (a + bb) + (cc + dd);
        s2 += (a * a + bb * bb) + (cc * cc + dd * dd);
    }
    __shared__ double ss[256], ss2[256];
    ss[threadIdx.x] = s; ss2[threadIdx.x] = s2;
    __syncthreads();
    for (int st = 128; st > 0; st >>= 1) {
        if (threadIdx.x < st) {
            ss[threadIdx.x]  += ss[threadIdx.x + st];
            ss2[threadIdx.x] += ss2[threadIdx.x + st];
        }
        __syncthreads();
    }
    if (threadIdx.x == 0) {
        g_ps [c * 64 + b] = ss[0];
        g_ps2[c * 64 + b] = ss2[0];
    }
}

__global__ void bn_finalize_kernel(const float* __restrict__ g,
                                   const float* __restrict__ be, int C, double n)
{
    int c = threadIdx.x;
    if (c >= C) return;
    double s = 0.0, s2 = 0.0;
    for (int b = 0; b < 64; b++) { s += g_ps[c * 64 + b]; s2 += g_ps2[c * 64 + b]; }
    double mean = s / n;
    double var  = s2 / n - mean * mean;
    float invf = g[c] / sqrtf((float)var + 1e-5f);
    g_inv[c]   = invf;
    g_shift[c] = be[c] - (float)mean * invf;
}

// ---------------------------------------------------------------------------
// BN apply + LIF scan over T (no pool).  y layout [(t*128+n),C,HW].
// ---------------------------------------------------------------------------
__global__ void bn_lif_kernel(const float* __restrict__ y, float* __restrict__ s,
                              int C, int HW, long tstride)
{
    const int sites = 128 * C * HW;
    const int idx = blockIdx.x * 256 + threadIdx.x;
    if (idx >= sites) return;
    const int c = (idx / HW) % C;
    const float vi = g_inv[c], sh = g_shift[c];
    float v = 0.f;
#pragma unroll
    for (int t = 0; t < TSTEPS; t++) {
        float x = fmaf(y[(size_t)t * tstride + idx], vi, sh);
        v = v + (x - v) * 0.5f;
        float spike = (v >= 1.0f) ? 1.0f : 0.0f;
        s[(size_t)sites * t + idx] = spike;
        if (v >= 1.0f) v = 0.0f;
    }
}

// ---------------------------------------------------------------------------
// BN apply + LIF + 2x2 maxpool fused.  Thread owns a 2x2 quad (4 v states),
// writes one pooled spike per timestep.
// ---------------------------------------------------------------------------
__global__ void bn_lif_pool_kernel(const float* __restrict__ y, float* __restrict__ out,
                                   int C, int H, int W)
{
    const int OH = H / 2, OW = W / 2;
    const int ohw = OH * OW;
    const int sites = 128 * C * ohw;
    const int idx = blockIdx.x * 256 + threadIdx.x;
    if (idx >= sites) return;
    const int c = (idx / ohw) % C;
    const int n = idx / (C * ohw);
    const int r = idx % ohw;
    const int oy = r / OW, ox = r % OW;
    const size_t base = ((size_t)(n * C + c) * H + 2 * oy) * W + 2 * ox;
    const long tstr = (long)128 * C * H * W;
    const float vi = g_inv[c], sh = g_shift[c];
    float v0 = 0.f, v1 = 0.f, v2 = 0.f, v3 = 0.f;
#pragma unroll
    for (int t = 0; t < TSTEPS; t++) {
        const float* p = y + (size_t)t * tstr + base;
        float x0 = fmaf(p[0],     vi, sh);
        float x1 = fmaf(p[1],     vi, sh);
        float x2 = fmaf(p[W],     vi, sh);
        float x3 = fmaf(p[W + 1], vi, sh);
        v0 = v0 + (x0 - v0) * 0.5f;
        v1 = v1 + (x1 - v1) * 0.5f;
        v2 = v2 + (x2 - v2) * 0.5f;
        v3 = v3 + (x3 - v3) * 0.5f;
        float sp = ((v0 >= 1.0f) || (v1 >= 1.0f) || (v2 >= 1.0f) || (v3 >= 1.0f)) ? 1.0f : 0.0f;
        out[(size_t)t * sites + idx] = sp;
        if (v0 >= 1.0f) v0 = 0.0f;
        if (v1 >= 1.0f) v1 = 0.0f;
        if (v2 >= 1.0f) v2 = 0.0f;
        if (v3 >= 1.0f) v3 = 0.0f;
    }
}

// ---------------------------------------------------------------------------
// fc1: [1024,2048] x [128,2048]^T.  Block = 4 rows x 128 out-features.
// ---------------------------------------------------------------------------
__global__ __launch_bounds__(128)
void fc1_kernel(const float* __restrict__ in, const float* __restrict__ w,
                const float* __restrict__ b, float* __restrict__ out)
{
    __shared__ float4 s_in[4][512];
    const int r0 = blockIdx.x * 4;
    for (int i = threadIdx.x; i < 4 * 512; i += 128) {
        int rr = i / 512, ff = i % 512;
        s_in[rr][ff] = ((const float4*)in)[(size_t)(r0 + rr) * 512 + ff];
    }
    __syncthreads();
    const int o = threadIdx.x;
    const float4* wr = (const float4*)(w + (size_t)o * 2048);
    float a0 = 0.f, a1 = 0.f, a2 = 0.f, a3 = 0.f;
#pragma unroll 4
    for (int f = 0; f < 512; f++) {
        float4 wv = wr[f];
        float4 x0 = s_in[0][f], x1 = s_in[1][f], x2 = s_in[2][f], x3 = s_in[3][f];
        a0 = fmaf(x0.x, wv.x, fmaf(x0.y, wv.y, fmaf(x0.z, wv.z, fmaf(x0.w, wv.w, a0))));
        a1 = fmaf(x1.x, wv.x, fmaf(x1.y, wv.y, fmaf(x1.z, wv.z, fmaf(x1.w, wv.w, a1))));
        a2 = fmaf(x2.x, wv.x, fmaf(x2.y, wv.y, fmaf(x2.z, wv.z, fmaf(x2.w, wv.w, a2))));
        a3 = fmaf(x3.x, wv.x, fmaf(x3.y, wv.y, fmaf(x3.z, wv.z, fmaf(x3.w, wv.w, a3))));
    }
    const float bo = b[o];
    out[(size_t)(r0 + 0) * 128 + o] = a0 + bo;
    out[(size_t)(r0 + 1) * 128 + o] = a1 + bo;
    out[(size_t)(r0 + 2) * 128 + o] = a2 + bo;
    out[(size_t)(r0 + 3) * 128 + o] = a3 + bo;
}

// fc2: [1024,128] x [10,128]^T
__global__ void fc2_kernel(const float* __restrict__ in, const float* __restrict__ w,
                           const float* __restrict__ b, float* __restrict__ out)
{
    const int idx = blockIdx.x * 256 + threadIdx.x;
    if (idx >= 10240) return;
    const int r = idx / 10, o = idx % 10;
    const float4* ir = (const float4*)(in + (size_t)r * 128);
    const float4* wr = (const float4*)(w + (size_t)o * 128);
    float a = 0.f;
#pragma unroll
    for (int f = 0; f < 32; f++) {
        float4 x = ir[f], wv = wr[f];
        a = fmaf(x.x, wv.x, fmaf(x.y, wv.y, fmaf(x.z, wv.z, fmaf(x.w, wv.w, a))));
    }
    out[idx] = a + b[o];
}

__global__ void lif_kernel(const float* __restrict__ y, float* __restrict__ s, int sites)
{
    const int idx = blockIdx.x * 256 + threadIdx.x;
    if (idx >= sites) return;
    float v = 0.f;
#pragma unroll
    for (int t = 0; t < TSTEPS; t++) {
        float x = y[(size_t)t * sites + idx];
        v = v + (x - v) * 0.5f;
        float spike = (v >= 1.0f) ? 1.0f : 0.0f;
        s[(size_t)t * sites + idx] = spike;
        if (v >= 1.0f) v = 0.0f;
    }
}

__global__ void lif_mean_kernel(const float* __restrict__ y, float* __restrict__ out,
                                int sites)
{
    const int idx = blockIdx.x * 256 + threadIdx.x;
    if (idx >= sites) return;
    float v = 0.f, cnt = 0.f;
#pragma unroll
    for (int t = 0; t < TSTEPS; t++) {
        float x = y[(size_t)t * sites + idx];
        v = v + (x - v) * 0.5f;
        if (v >= 1.0f) { cnt += 1.0f; v = 0.0f; }
    }
    out[idx] = cnt * 0.125f;
}

// ---------------------------------------------------------------------------
extern "C" void kernel_launch(void* const* d_in, const int* in_sizes, int n_in,
                              void* d_out, int out_size)
{
    const float* x = (const float*)d_in[0];
    const float* w[7];  const float* bb[7];  const float* gg[7];  const float* be[7];
    for (int L = 1; L <= 6; L++) {
        w [L] = (const float*)d_in[1 + 4 * (L - 1) + 0];
        bb[L] = (const float*)d_in[1 + 4 * (L - 1) + 1];
        gg[L] = (const float*)d_in[1 + 4 * (L - 1) + 2];
        be[L] = (const float*)d_in[1 + 4 * (L - 1) + 3];
    }
    const float* fc1_w = (const float*)d_in[25];
    const float* fc1_b = (const float*)d_in[26];
    const float* fc2_w = (const float*)d_in[27];
    const float* fc2_b = (const float*)d_in[28];
    float* out = (float*)d_out;

    float *y, *s, *sp, *f1, *f1s, *f2;
    cudaGetSymbolAddress((void**)&y,   g_y);
    cudaGetSymbolAddress((void**)&s,   g_s);
    cudaGetSymbolAddress((void**)&sp,  g_sp);
    cudaGetSymbolAddress((void**)&f1,  g_fc1);
    cudaGetSymbolAddress((void**)&f1s, g_fc1s);
    cudaGetSymbolAddress((void**)&f2,  g_fc2);

    // ---- Layer 1 (input identical across T: conv over 128 imgs only) ----
    conv3x3_kernel<3, 32, 32, 32, 1, 3><<<dim3(128, 4), 256>>>(x, w[1], bb[1], y);
    bn_stats_kernel<<<dim3(32, 64), 256>>>(y, 32, 256, 128);
    bn_finalize_kernel<<<1, 128>>>(gg[1], be[1], 32, 128.0 * 1024.0);
    bn_lif_kernel<<<16384, 256>>>(y, s, 32, 1024, 0);

    // ---- Layer 2 (+pool) ----
    conv3x3_kernel<32, 32, 32, 32, 1, 4><<<dim3(1024, 4), 256>>>(s, w[2], bb[2], y);
    bn_stats_kernel<<<dim3(32, 64), 256>>>(y, 32, 256, 1024);
    bn_finalize_kernel<<<1, 128>>>(gg[2], be[2], 32, 1024.0 * 1024.0);
    bn_lif_pool_kernel<<<4096, 256>>>(y, sp, 32, 32, 32);

    // ---- Layer 3 ----
    conv3x3_kernel<32, 64, 16, 16, 4, 4><<<dim3(256, 8), 256>>>(sp, w[3], bb[3], y);
    bn_stats_kernel<<<dim3(64, 64), 256>>>(y, 64, 64, 1024);
    bn_finalize_kernel<<<1, 128>>>(gg[3], be[3], 64, 1024.0 * 256.0);
    bn_lif_kernel<<<8192, 256>>>(y, s, 64, 256, (long)128 * 64 * 256);

    // ---- Layer 4 (+pool) ----
    conv3x3_kernel<64, 64, 16, 16, 4, 4><<<dim3(256, 8), 256>>>(s, w[4], bb[4], y);
    bn_stats_kernel<<<dim3(64, 64), 256>>>(y, 64, 64, 1024);
    bn_finalize_kernel<<<1, 128>>>(gg[4], be[4], 64, 1024.0 * 256.0);
    bn_lif_pool_kernel<<<2048, 256>>>(y, sp, 64, 16, 16);

    // ---- Layer 5 ----
    conv3x3_kernel<64, 128, 8, 8, 16, 4><<<dim3(64, 16), 256>>>(sp, w[5], bb[5], y);
    bn_stats_kernel<<<dim3(128, 64), 256>>>(y, 128, 16, 1024);
    bn_finalize_kernel<<<1, 128>>>(gg[5], be[5], 128, 1024.0 * 64.0);
    bn_lif_kernel<<<4096, 256>>>(y, s, 128, 64, (long)128 * 128 * 64);

    // ---- Layer 6 (+pool) ----
    conv3x3_kernel<128, 128, 8, 8, 16, 4><<<dim3(64, 16), 256>>>(s, w[6], bb[6], y);
    bn_stats_kernel<<<dim3(128, 64), 256>>>(y, 128, 16, 1024);
    bn_finalize_kernel<<<1, 128>>>(gg[6], be[6], 128, 1024.0 * 64.0);
    bn_lif_pool_kernel<<<1024, 256>>>(y, sp, 128, 8, 8);

    // ---- FC head ----
    fc1_kernel<<<256, 128>>>(sp, fc1_w, fc1_b, f1);
    lif_kernel<<<64, 256>>>(f1, f1s, 16384);
    fc2_kernel<<<40, 256>>>(f1s, fc2_w, fc2_b, f2);
    lif_mean_kernel<<<5, 256>>>(f2, out, 1280);
}

// round 5
// speedup vs baseline: 2.0839x; 1.5525x over previous
#include <cuda_runtime.h>
#include <math.h>

// ---------------------------------------------------------------------------
// EnhancedSNNCifar: T=8 SNN forward, fp32 throughout.
// R2: staging index math hoisted out of the channel loop (precomputed per-
//     thread position tables), CH=8 chunks for big layers, fewer syncs.
// ---------------------------------------------------------------------------

#define TSTEPS 8

__device__ float  g_y [33554432];
__device__ float  g_s [33554432];
__device__ float  g_sp[ 8388608];
__device__ float  g_fc1 [131072];
__device__ float  g_fc1s[131072];
__device__ float  g_fc2 [ 10240];
__device__ double g_ps [128 * 64];
__device__ double g_ps2[128 * 64];
__device__ float  g_inv  [128];
__device__ float  g_shift[128];

// ---------------------------------------------------------------------------
// Direct 3x3 conv, pad=1, stride=1.  Thread: 2x2 pixels x 8 couts.
// Block = 256 threads = IMGS images * QPI quads.  CH input channels staged
// per sync round.  All staging index math precomputed before the main loop.
// ---------------------------------------------------------------------------
template<int CIN, int COUT, int H, int W, int IMGS, int CH>
__global__ __launch_bounds__(256)
void conv3x3_kernel(const float* __restrict__ in, const float* __restrict__ wt,
                    const float* __restrict__ bias, float* __restrict__ out)
{
    constexpr int QPI = (H / 2) * (W / 2);
    static_assert(IMGS * QPI == 256, "block mapping");
    constexpr int PW = W + 2, PH = H + 2;
    constexpr int IN_TILE = PH * PW;
    constexpr int HW = H * W;
    constexpr int TOT = IMGS * IN_TILE;
    constexpr int NPOS = (TOT + 255) / 256;

    __shared__ float s_in[CH][TOT];
    __shared__ __align__(16) float s_w[CH][9][8];

    const int tid = threadIdx.x;
    const int cog = blockIdx.y;
    const int m0  = blockIdx.x * IMGS;

    // ---- precompute staging tables (once) ----
    int  gpix[NPOS];      // gmem offset rel. to (image m0, channel 0)
    bool pval[NPOS];      // interior (load) vs halo (store 0)
#pragma unroll
    for (int k = 0; k < NPOS; k++) {
        const int i = tid + k * 256;
        const int il = i / IN_TILE, r = i % IN_TILE;
        const int py = r / PW, px = r % PW;
        const int iy = py - 1, ix = px - 1;
        pval[k] = (i < TOT) && (iy >= 0) && (iy < H) && (ix >= 0) && (ix < W);
        gpix[k] = il * (CIN * HW) + iy * W + ix;
    }
    // weight slot (threads 0..71)
    const int wj = tid / 9, wk = tid % 9;
    const int wbase = ((cog * 8 + wj) * CIN) * 9 + wk;

    const int img_l = tid / QPI;
    const int q     = tid % QPI;
    const int qy = q / (W / 2), qx = q % (W / 2);
    const int oy = qy * 2, ox = qx * 2;
    const float* inb = in + (size_t)m0 * CIN * HW;

    float acc[4][8];
#pragma unroll
    for (int p = 0; p < 4; p++)
#pragma unroll
        for (int j = 0; j < 8; j++) acc[p][j] = 0.f;

#pragma unroll 1
    for (int c0 = 0; c0 < CIN; c0 += CH) {
        __syncthreads();
        if (tid < 72) {
#pragma unroll
            for (int c = 0; c < CH; c++)
                s_w[c][wk][wj] = wt[wbase + (c0 + c) * 9];
        }
#pragma unroll
        for (int c = 0; c < CH; c++) {
            const float* inc = inb + (size_t)(c0 + c) * HW;
#pragma unroll
            for (int k = 0; k < NPOS; k++) {
                const int i = tid + k * 256;
                if (i < TOT)
                    s_in[c][i] = pval[k] ? __ldg(inc + gpix[k]) : 0.f;
            }
        }
        __syncthreads();

#pragma unroll 1
        for (int c = 0; c < CH; ++c) {
            float xv[4][4];
            const float* sb = &s_in[c][img_l * IN_TILE + oy * PW + ox];
#pragma unroll
            for (int dy = 0; dy < 4; dy++) {
                float2 a = *(const float2*)(sb + dy * PW);
                float2 b = *(const float2*)(sb + dy * PW + 2);
                xv[dy][0] = a.x; xv[dy][1] = a.y; xv[dy][2] = b.x; xv[dy][3] = b.y;
            }
#pragma unroll
            for (int k = 0; k < 9; k++) {
                const int ky = k / 3, kx = k % 3;
                float4 wlo = *(const float4*)&s_w[c][k][0];
                float4 whi = *(const float4*)&s_w[c][k][4];
                float w8[8] = {wlo.x, wlo.y, wlo.z, wlo.w, whi.x, whi.y, whi.z, whi.w};
#pragma unroll
                for (int py = 0; py < 2; py++)
#pragma unroll
                    for (int px = 0; px < 2; px++) {
                        const float xvv = xv[py + ky][px + kx];
#pragma unroll
                        for (int j = 0; j < 8; j++)
                            acc[py * 2 + px][j] = fmaf(xvv, w8[j], acc[py * 2 + px][j]);
                    }
            }
        }
    }

    float bj[8];
#pragma unroll
    for (int j = 0; j < 8; j++) bj[j] = bias[cog * 8 + j];

#pragma unroll
    for (int j = 0; j < 8; j++) {
        const int co = cog * 8 + j;
        const size_t base = ((size_t)(m0 + img_l) * COUT + co) * HW;
#pragma unroll
        for (int py = 0; py < 2; py++) {
            float2 v2 = make_float2(acc[py * 2 + 0][j] + bj[j], acc[py * 2 + 1][j] + bj[j]);
            *(float2*)&out[base + (oy + py) * W + ox] = v2;
        }
    }
}

// ---------------------------------------------------------------------------
__global__ void bn_stats_kernel(const float* __restrict__ y, int C, int HW4, int M)
{
    const int c = blockIdx.x, b = blockIdx.y;
    const long total4 = (long)M * HW4;
    const long chunk = (total4 + 63) / 64;
    long beg = (long)b * chunk;
    long end = beg + chunk; if (end > total4) end = total4;

    const float4* y4 = (const float4*)y;
    double s = 0.0, s2 = 0.0;
    for (long e = beg + threadIdx.x; e < end; e += 256) {
        long m = e / HW4; int off = (int)(e % HW4);
        float4 v = y4[((size_t)m * C + c) * HW4 + off];
        double a = v.x, bb = v.y, cc = v.z, dd = v.w;
        s += (a + bb) + (cc + dd);
        s2 += (a * a + bb * bb) + (cc * cc + dd * dd);
    }
    __shared__ double ss[256], ss2[256];
    ss[threadIdx.x] = s; ss2[threadIdx.x] = s2;
    __syncthreads();
    for (int st = 128; st > 0; st >>= 1) {
        if (threadIdx.x < st) {
            ss[threadIdx.x]  += ss[threadIdx.x + st];
            ss2[threadIdx.x] += ss2[threadIdx.x + st];
        }
        __syncthreads();
    }
    if (threadIdx.x == 0) {
        g_ps [c * 64 + b] = ss[0];
        g_ps2[c * 64 + b] = ss2[0];
    }
}

__global__ void bn_finalize_kernel(const float* __restrict__ g,
                                   const float* __restrict__ be, int C, double n)
{
    int c = threadIdx.x;
    if (c >= C) return;
    double s = 0.0, s2 = 0.0;
    for (int b = 0; b < 64; b++) { s += g_ps[c * 64 + b]; s2 += g_ps2[c * 64 + b]; }
    double mean = s / n;
    double var  = s2 / n - mean * mean;
    float invf = g[c] / sqrtf((float)var + 1e-5f);
    g_inv[c]   = invf;
    g_shift[c] = be[c] - (float)mean * invf;
}

__global__ void bn_lif_kernel(const float* __restrict__ y, float* __restrict__ s,
                              int C, int HW, long tstride)
{
    const int sites = 128 * C * HW;
    const int idx = blockIdx.x * 256 + threadIdx.x;
    if (idx >= sites) return;
    const int c = (idx / HW) % C;
    const float vi = g_inv[c], sh = g_shift[c];
    float v = 0.f;
#pragma unroll
    for (int t = 0; t < TSTEPS; t++) {
        float x = fmaf(y[(size_t)t * tstride + idx], vi, sh);
        v = v + (x - v) * 0.5f;
        float spike = (v >= 1.0f) ? 1.0f : 0.0f;
        s[(size_t)sites * t + idx] = spike;
        if (v >= 1.0f) v = 0.0f;
    }
}

__global__ void bn_lif_pool_kernel(const float* __restrict__ y, float* __restrict__ out,
                                   int C, int H, int W)
{
    const int OH = H / 2, OW = W / 2;
    const int ohw = OH * OW;
    const int sites = 128 * C * ohw;
    const int idx = blockIdx.x * 256 + threadIdx.x;
    if (idx >= sites) return;
    const int c = (idx / ohw) % C;
    const int n = idx / (C * ohw);
    const int r = idx % ohw;
    const int oy = r / OW, ox = r % OW;
    const size_t base = ((size_t)(n * C + c) * H + 2 * oy) * W + 2 * ox;
    const long tstr = (long)128 * C * H * W;
    const float vi = g_inv[c], sh = g_shift[c];
    float v0 = 0.f, v1 = 0.f, v2 = 0.f, v3 = 0.f;
#pragma unroll
    for (int t = 0; t < TSTEPS; t++) {
        const float* p = y + (size_t)t * tstr + base;
        float x0 = fmaf(p[0],     vi, sh);
        float x1 = fmaf(p[1],     vi, sh);
        float x2 = fmaf(p[W],     vi, sh);
        float x3 = fmaf(p[W + 1], vi, sh);
        v0 = v0 + (x0 - v0) * 0.5f;
        v1 = v1 + (x1 - v1) * 0.5f;
        v2 = v2 + (x2 - v2) * 0.5f;
        v3 = v3 + (x3 - v3) * 0.5f;
        float sp = ((v0 >= 1.0f) || (v1 >= 1.0f) || (v2 >= 1.0f) || (v3 >= 1.0f)) ? 1.0f : 0.0f;
        out[(size_t)t * sites + idx] = sp;
        if (v0 >= 1.0f) v0 = 0.0f;
        if (v1 >= 1.0f) v1 = 0.0f;
        if (v2 >= 1.0f) v2 = 0.0f;
        if (v3 >= 1.0f) v3 = 0.0f;
    }
}

__global__ __launch_bounds__(128)
void fc1_kernel(const float* __restrict__ in, const float* __restrict__ w,
                const float* __restrict__ b, float* __restrict__ out)
{
    __shared__ float4 s_in[4][512];
    const int r0 = blockIdx.x * 4;
    for (int i = threadIdx.x; i < 4 * 512; i += 128) {
        int rr = i / 512, ff = i % 512;
        s_in[rr][ff] = ((const float4*)in)[(size_t)(r0 + rr) * 512 + ff];
    }
    __syncthreads();
    const int o = threadIdx.x;
    const float4* wr = (const float4*)(w + (size_t)o * 2048);
    float a0 = 0.f, a1 = 0.f, a2 = 0.f, a3 = 0.f;
#pragma unroll 4
    for (int f = 0; f < 512; f++) {
        float4 wv = wr[f];
        float4 x0 = s_in[0][f], x1 = s_in[1][f], x2 = s_in[2][f], x3 = s_in[3][f];
        a0 = fmaf(x0.x, wv.x, fmaf(x0.y, wv.y, fmaf(x0.z, wv.z, fmaf(x0.w, wv.w, a0))));
        a1 = fmaf(x1.x, wv.x, fmaf(x1.y, wv.y, fmaf(x1.z, wv.z, fmaf(x1.w, wv.w, a1))));
        a2 = fmaf(x2.x, wv.x, fmaf(x2.y, wv.y, fmaf(x2.z, wv.z, fmaf(x2.w, wv.w, a2))));
        a3 = fmaf(x3.x, wv.x, fmaf(x3.y, wv.y, fmaf(x3.z, wv.z, fmaf(x3.w, wv.w, a3))));
    }
    const float bo = b[o];
    out[(size_t)(r0 + 0) * 128 + o] = a0 + bo;
    out[(size_t)(r0 + 1) * 128 + o] = a1 + bo;
    out[(size_t)(r0 + 2) * 128 + o] = a2 + bo;
    out[(size_t)(r0 + 3) * 128 + o] = a3 + bo;
}

__global__ void fc2_kernel(const float* __restrict__ in, const float* __restrict__ w,
                           const float* __restrict__ b, float* __restrict__ out)
{
    const int idx = blockIdx.x * 256 + threadIdx.x;
    if (idx >= 10240) return;
    const int r = idx / 10, o = idx % 10;
    const float4* ir = (const float4*)(in + (size_t)r * 128);
    const float4* wr = (const float4*)(w + (size_t)o * 128);
    float a = 0.f;
#pragma unroll
    for (int f = 0; f < 32; f++) {
        float4 x = ir[f], wv = wr[f];
        a = fmaf(x.x, wv.x, fmaf(x.y, wv.y, fmaf(x.z, wv.z, fmaf(x.w, wv.w, a))));
    }
    out[idx] = a + b[o];
}

__global__ void lif_kernel(const float* __restrict__ y, float* __restrict__ s, int sites)
{
    const int idx = blockIdx.x * 256 + threadIdx.x;
    if (idx >= sites) return;
    float v = 0.f;
#pragma unroll
    for (int t = 0; t < TSTEPS; t++) {
        float x = y[(size_t)t * sites + idx];
        v = v + (x - v) * 0.5f;
        float spike = (v >= 1.0f) ? 1.0f : 0.0f;
        s[(size_t)t * sites + idx] = spike;
        if (v >= 1.0f) v = 0.0f;
    }
}

__global__ void lif_mean_kernel(const float* __restrict__ y, float* __restrict__ out,
                                int sites)
{
    const int idx = blockIdx.x * 256 + threadIdx.x;
    if (idx >= sites) return;
    float v = 0.f, cnt = 0.f;
#pragma unroll
    for (int t = 0; t < TSTEPS; t++) {
        float x = y[(size_t)t * sites + idx];
        v = v + (x - v) * 0.5f;
        if (v >= 1.0f) { cnt += 1.0f; v = 0.0f; }
    }
    out[idx] = cnt * 0.125f;
}

// ---------------------------------------------------------------------------
extern "C" void kernel_launch(void* const* d_in, const int* in_sizes, int n_in,
                              void* d_out, int out_size)
{
    const float* x = (const float*)d_in[0];
    const float* w[7];  const float* bb[7];  const float* gg[7];  const float* be[7];
    for (int L = 1; L <= 6; L++) {
        w [L] = (const float*)d_in[1 + 4 * (L - 1) + 0];
        bb[L] = (const float*)d_in[1 + 4 * (L - 1) + 1];
        gg[L] = (const float*)d_in[1 + 4 * (L - 1) + 2];
        be[L] = (const float*)d_in[1 + 4 * (L - 1) + 3];
    }
    const float* fc1_w = (const float*)d_in[25];
    const float* fc1_b = (const float*)d_in[26];
    const float* fc2_w = (const float*)d_in[27];
    const float* fc2_b = (const float*)d_in[28];
    float* out = (float*)d_out;

    float *y, *s, *sp, *f1, *f1s, *f2;
    cudaGetSymbolAddress((void**)&y,   g_y);
    cudaGetSymbolAddress((void**)&s,   g_s);
    cudaGetSymbolAddress((void**)&sp,  g_sp);
    cudaGetSymbolAddress((void**)&f1,  g_fc1);
    cudaGetSymbolAddress((void**)&f1s, g_fc1s);
    cudaGetSymbolAddress((void**)&f2,  g_fc2);

    // ---- Layer 1 ----
    conv3x3_kernel<3, 32, 32, 32, 1, 3><<<dim3(128, 4), 256>>>(x, w[1], bb[1], y);
    bn_stats_kernel<<<dim3(32, 64), 256>>>(y, 32, 256, 128);
    bn_finalize_kernel<<<1, 128>>>(gg[1], be[1], 32, 128.0 * 1024.0);
    bn_lif_kernel<<<16384, 256>>>(y, s, 32, 1024, 0);

    // ---- Layer 2 (+pool) ----
    conv3x3_kernel<32, 32, 32, 32, 1, 8><<<dim3(1024, 4), 256>>>(s, w[2], bb[2], y);
    bn_stats_kernel<<<dim3(32, 64), 256>>>(y, 32, 256, 1024);
    bn_finalize_kernel<<<1, 128>>>(gg[2], be[2], 32, 1024.0 * 1024.0);
    bn_lif_pool_kernel<<<4096, 256>>>(y, sp, 32, 32, 32);

    // ---- Layer 3 ----
    conv3x3_kernel<32, 64, 16, 16, 4, 8><<<dim3(256, 8), 256>>>(sp, w[3], bb[3], y);
    bn_stats_kernel<<<dim3(64, 64), 256>>>(y, 64, 64, 1024);
    bn_finalize_kernel<<<1, 128>>>(gg[3], be[3], 64, 1024.0 * 256.0);
    bn_lif_kernel<<<8192, 256>>>(y, s, 64, 256, (long)128 * 64 * 256);

    // ---- Layer 4 (+pool) ----
    conv3x3_kernel<64, 64, 16, 16, 4, 8><<<dim3(256, 8), 256>>>(s, w[4], bb[4], y);
    bn_stats_kernel<<<dim3(64, 64), 256>>>(y, 64, 64, 1024);
    bn_finalize_kernel<<<1, 128>>>(gg[4], be[4], 64, 1024.0 * 256.0);
    bn_lif_pool_kernel<<<2048, 256>>>(y, sp, 64, 16, 16);

    // ---- Layer 5 ----
    conv3x3_kernel<64, 128, 8, 8, 16, 4><<<dim3(64, 16), 256>>>(sp, w[5], bb[5], y);
    bn_stats_kernel<<<dim3(128, 64), 256>>>(y, 128, 16, 1024);
    bn_finalize_kernel<<<1, 128>>>(gg[5], be[5], 128, 1024.0 * 64.0);
    bn_lif_kernel<<<4096, 256>>>(y, s, 128, 64, (long)128 * 128 * 64);

    // ---- Layer 6 (+pool) ----
    conv3x3_kernel<128, 128, 8, 8, 16, 4><<<dim3(64, 16), 256>>>(s, w[6], bb[6], y);
    bn_stats_kernel<<<dim3(128, 64), 256>>>(y, 128, 16, 1024);
    bn_finalize_kernel<<<1, 128>>>(gg[6], be[6], 128, 1024.0 * 64.0);
    bn_lif_pool_kernel<<<1024, 256>>>(y, sp, 128, 8, 8);

    // ---- FC head ----
    fc1_kernel<<<256, 128>>>(sp, fc1_w, fc1_b, f1);
    lif_kernel<<<64, 256>>>(f1, f1s, 16384);
    fc2_kernel<<<40, 256>>>(f1s, fc2_w, fc2_b, f2);
    lif_mean_kernel<<<5, 256>>>(f2, out, 1280);
}

// round 6
// speedup vs baseline: 2.2507x; 1.0801x over previous
#include <cuda_runtime.h>
#include <math.h>

// ---------------------------------------------------------------------------
// EnhancedSNNCifar: T=8 SNN forward, fp32 throughout.
// R5: conv inner loop rewritten with packed fp32x2 FMAs (fma.rn.f32x2,
//     Blackwell FFMA2 path) — pairs of output channels per instruction.
//     Bit-identical accumulation order vs scalar version.
// ---------------------------------------------------------------------------

#define TSTEPS 8

typedef unsigned long long ull;

__device__ float  g_y [33554432];
__device__ float  g_s [33554432];
__device__ float  g_sp[ 8388608];
__device__ float  g_fc1 [131072];
__device__ float  g_fc1s[131072];
__device__ float  g_fc2 [ 10240];
__device__ double g_ps [128 * 64];
__device__ double g_ps2[128 * 64];
__device__ float  g_inv  [128];
__device__ float  g_shift[128];

__device__ __forceinline__ ull ffma2(ull a, ull b, ull c) {
    ull d;
    asm("fma.rn.f32x2 %0, %1, %2, %3;" : "=l"(d) : "l"(a), "l"(b), "l"(c));
    return d;
}
__device__ __forceinline__ ull pack2(float x) {
    ull d;
    asm("mov.b64 %0, {%1, %1};" : "=l"(d) : "f"(x));
    return d;
}
__device__ __forceinline__ void unpack2(ull v, float& lo, float& hi) {
    asm("mov.b64 {%0, %1}, %2;" : "=f"(lo), "=f"(hi) : "l"(v));
}

// ---------------------------------------------------------------------------
// Direct 3x3 conv, pad=1, stride=1.  Thread: 2x2 pixels x 8 couts (4 f32x2
// accumulator pairs).  Block = 256 threads = IMGS images * QPI quads.
// CH input channels staged per sync round; staging index math precomputed.
// ---------------------------------------------------------------------------
template<int CIN, int COUT, int H, int W, int IMGS, int CH>
__global__ __launch_bounds__(256)
void conv3x3_kernel(const float* __restrict__ in, const float* __restrict__ wt,
                    const float* __restrict__ bias, float* __restrict__ out)
{
    constexpr int QPI = (H / 2) * (W / 2);
    static_assert(IMGS * QPI == 256, "block mapping");
    constexpr int PW = W + 2, PH = H + 2;
    constexpr int IN_TILE = PH * PW;
    constexpr int HW = H * W;
    constexpr int TOT = IMGS * IN_TILE;
    constexpr int NPOS = (TOT + 255) / 256;

    __shared__ float s_in[CH][TOT];
    __shared__ __align__(16) float s_w[CH][9][8];

    const int tid = threadIdx.x;
    const int cog = blockIdx.y;
    const int m0  = blockIdx.x * IMGS;

    // ---- precompute staging tables (once) ----
    int  gpix[NPOS];
    bool pval[NPOS];
#pragma unroll
    for (int k = 0; k < NPOS; k++) {
        const int i = tid + k * 256;
        const int il = i / IN_TILE, r = i % IN_TILE;
        const int py = r / PW, px = r % PW;
        const int iy = py - 1, ix = px - 1;
        pval[k] = (i < TOT) && (iy >= 0) && (iy < H) && (ix >= 0) && (ix < W);
        gpix[k] = il * (CIN * HW) + iy * W + ix;
    }
    const int wj = tid / 9, wk = tid % 9;
    const int wbase = ((cog * 8 + wj) * CIN) * 9 + wk;

    const int img_l = tid / QPI;
    const int q     = tid % QPI;
    const int qy = q / (W / 2), qx = q % (W / 2);
    const int oy = qy * 2, ox = qx * 2;
    const float* inb = in + (size_t)m0 * CIN * HW;

    // acc2[pos][p] : pos = 2x2 pixel, p = cout pair (couts 2p, 2p+1)
    ull acc2[4][4];
#pragma unroll
    for (int p = 0; p < 4; p++)
#pragma unroll
        for (int j = 0; j < 4; j++) acc2[p][j] = 0ULL;

#pragma unroll 1
    for (int c0 = 0; c0 < CIN; c0 += CH) {
        __syncthreads();
        if (tid < 72) {
#pragma unroll
            for (int c = 0; c < CH; c++)
                s_w[c][wk][wj] = wt[wbase + (c0 + c) * 9];
        }
#pragma unroll
        for (int c = 0; c < CH; c++) {
            const float* inc = inb + (size_t)(c0 + c) * HW;
#pragma unroll
            for (int k = 0; k < NPOS; k++) {
                const int i = tid + k * 256;
                if (i < TOT)
                    s_in[c][i] = pval[k] ? __ldg(inc + gpix[k]) : 0.f;
            }
        }
        __syncthreads();

#pragma unroll 1
        for (int c = 0; c < CH; ++c) {
            // 4x4 input window, broadcast-packed into f32x2
            ull xp[4][4];
            const float* sb = &s_in[c][img_l * IN_TILE + oy * PW + ox];
#pragma unroll
            for (int dy = 0; dy < 4; dy++) {
                float2 a = *(const float2*)(sb + dy * PW);
                float2 b = *(const float2*)(sb + dy * PW + 2);
                xp[dy][0] = pack2(a.x); xp[dy][1] = pack2(a.y);
                xp[dy][2] = pack2(b.x); xp[dy][3] = pack2(b.y);
            }
#pragma unroll
            for (int k = 0; k < 9; k++) {
                const int ky = k / 3, kx = k % 3;
                const ull* wp = (const ull*)&s_w[c][k][0];
                const ull w0 = wp[0], w1 = wp[1], w2 = wp[2], w3 = wp[3];
#pragma unroll
                for (int py = 0; py < 2; py++)
#pragma unroll
                    for (int px = 0; px < 2; px++) {
                        const ull xb = xp[py + ky][px + kx];
                        const int pos = py * 2 + px;
                        acc2[pos][0] = ffma2(xb, w0, acc2[pos][0]);
                        acc2[pos][1] = ffma2(xb, w1, acc2[pos][1]);
                        acc2[pos][2] = ffma2(xb, w2, acc2[pos][2]);
                        acc2[pos][3] = ffma2(xb, w3, acc2[pos][3]);
                    }
            }
        }
    }

    // unpack accumulators -> acc[pos][cout]
    float acc[4][8];
#pragma unroll
    for (int pos = 0; pos < 4; pos++)
#pragma unroll
        for (int p = 0; p < 4; p++)
            unpack2(acc2[pos][p], acc[pos][2 * p], acc[pos][2 * p + 1]);

    float bj[8];
#pragma unroll
    for (int j = 0; j < 8; j++) bj[j] = bias[cog * 8 + j];

#pragma unroll
    for (int j = 0; j < 8; j++) {
        const int co = cog * 8 + j;
        const size_t base = ((size_t)(m0 + img_l) * COUT + co) * HW;
#pragma unroll
        for (int py = 0; py < 2; py++) {
            float2 v2 = make_float2(acc[py * 2 + 0][j] + bj[j], acc[py * 2 + 1][j] + bj[j]);
            *(float2*)&out[base + (oy + py) * W + ox] = v2;
        }
    }
}

// ---------------------------------------------------------------------------
__global__ void bn_stats_kernel(const float* __restrict__ y, int C, int HW4, int M)
{
    const int c = blockIdx.x, b = blockIdx.y;
    const long total4 = (long)M * HW4;
    const long chunk = (total4 + 63) / 64;
    long beg = (long)b * chunk;
    long end = beg + chunk; if (end > total4) end = total4;

    const float4* y4 = (const float4*)y;
    double s = 0.0, s2 = 0.0;
    for (long e = beg + threadIdx.x; e < end; e += 256) {
        long m = e / HW4; int off = (int)(e % HW4);
        float4 v = y4[((size_t)m * C + c) * HW4 + off];
        double a = v.x, bb = v.y, cc = v.z, dd = v.w;
        s += (a + bb) + (cc + dd);
        s2 += (a * a + bb * bb) + (cc * cc + dd * dd);
    }
    __shared__ double ss[256], ss2[256];
    ss[threadIdx.x] = s; ss2[threadIdx.x] = s2;
    __syncthreads();
    for (int st = 128; st > 0; st >>= 1) {
        if (threadIdx.x < st) {
            ss[threadIdx.x]  += ss[threadIdx.x + st];
            ss2[threadIdx.x] += ss2[threadIdx.x + st];
        }
        __syncthreads();
    }
    if (threadIdx.x == 0) {
        g_ps [c * 64 + b] = ss[0];
        g_ps2[c * 64 + b] = ss2[0];
    }
}

__global__ void bn_finalize_kernel(const float* __restrict__ g,
                                   const float* __restrict__ be, int C, double n)
{
    int c = threadIdx.x;
    if (c >= C) return;
    double s = 0.0, s2 = 0.0;
    for (int b = 0; b < 64; b++) { s += g_ps[c * 64 + b]; s2 += g_ps2[c * 64 + b]; }
    double mean = s / n;
    double var  = s2 / n - mean * mean;
    float invf = g[c] / sqrtf((float)var + 1e-5f);
    g_inv[c]   = invf;
    g_shift[c] = be[c] - (float)mean * invf;
}

__global__ void bn_lif_kernel(const float* __restrict__ y, float* __restrict__ s,
                              int C, int HW, long tstride)
{
    const int sites = 128 * C * HW;
    const int idx = blockIdx.x * 256 + threadIdx.x;
    if (idx >= sites) return;
    const int c = (idx / HW) % C;
    const float vi = g_inv[c], sh = g_shift[c];
    float v = 0.f;
#pragma unroll
    for (int t = 0; t < TSTEPS; t++) {
        float x = fmaf(y[(size_t)t * tstride + idx], vi, sh);
        v = v + (x - v) * 0.5f;
        float spike = (v >= 1.0f) ? 1.0f : 0.0f;
        s[(size_t)sites * t + idx] = spike;
        if (v >= 1.0f) v = 0.0f;
    }
}

__global__ void bn_lif_pool_kernel(const float* __restrict__ y, float* __restrict__ out,
                                   int C, int H, int W)
{
    const int OH = H / 2, OW = W / 2;
    const int ohw = OH * OW;
    const int sites = 128 * C * ohw;
    const int idx = blockIdx.x * 256 + threadIdx.x;
    if (idx >= sites) return;
    const int c = (idx / ohw) % C;
    const int n = idx / (C * ohw);
    const int r = idx % ohw;
    const int oy = r / OW, ox = r % OW;
    const size_t base = ((size_t)(n * C + c) * H + 2 * oy) * W + 2 * ox;
    const long tstr = (long)128 * C * H * W;
    const float vi = g_inv[c], sh = g_shift[c];
    float v0 = 0.f, v1 = 0.f, v2 = 0.f, v3 = 0.f;
#pragma unroll
    for (int t = 0; t < TSTEPS; t++) {
        const float* p = y + (size_t)t * tstr + base;
        float x0 = fmaf(p[0],     vi, sh);
        float x1 = fmaf(p[1],     vi, sh);
        float x2 = fmaf(p[W],     vi, sh);
        float x3 = fmaf(p[W + 1], vi, sh);
        v0 = v0 + (x0 - v0) * 0.5f;
        v1 = v1 + (x1 - v1) * 0.5f;
        v2 = v2 + (x2 - v2) * 0.5f;
        v3 = v3 + (x3 - v3) * 0.5f;
        float sp = ((v0 >= 1.0f) || (v1 >= 1.0f) || (v2 >= 1.0f) || (v3 >= 1.0f)) ? 1.0f : 0.0f;
        out[(size_t)t * sites + idx] = sp;
        if (v0 >= 1.0f) v0 = 0.0f;
        if (v1 >= 1.0f) v1 = 0.0f;
        if (v2 >= 1.0f) v2 = 0.0f;
        if (v3 >= 1.0f) v3 = 0.0f;
    }
}

__global__ __launch_bounds__(128)
void fc1_kernel(const float* __restrict__ in, const float* __restrict__ w,
                const float* __restrict__ b, float* __restrict__ out)
{
    __shared__ float4 s_in[4][512];
    const int r0 = blockIdx.x * 4;
    for (int i = threadIdx.x; i < 4 * 512; i += 128) {
        int rr = i / 512, ff = i % 512;
        s_in[rr][ff] = ((const float4*)in)[(size_t)(r0 + rr) * 512 + ff];
    }
    __syncthreads();
    const int o = threadIdx.x;
    const float4* wr = (const float4*)(w + (size_t)o * 2048);
    float a0 = 0.f, a1 = 0.f, a2 = 0.f, a3 = 0.f;
#pragma unroll 4
    for (int f = 0; f < 512; f++) {
        float4 wv = wr[f];
        float4 x0 = s_in[0][f], x1 = s_in[1][f], x2 = s_in[2][f], x3 = s_in[3][f];
        a0 = fmaf(x0.x, wv.x, fmaf(x0.y, wv.y, fmaf(x0.z, wv.z, fmaf(x0.w, wv.w, a0))));
        a1 = fmaf(x1.x, wv.x, fmaf(x1.y, wv.y, fmaf(x1.z, wv.z, fmaf(x1.w, wv.w, a1))));
        a2 = fmaf(x2.x, wv.x, fmaf(x2.y, wv.y, fmaf(x2.z, wv.z, fmaf(x2.w, wv.w, a2))));
        a3 = fmaf(x3.x, wv.x, fmaf(x3.y, wv.y, fmaf(x3.z, wv.z, fmaf(x3.w, wv.w, a3))));
    }
    const float bo = b[o];
    out[(size_t)(r0 + 0) * 128 + o] = a0 + bo;
    out[(size_t)(r0 + 1) * 128 + o] = a1 + bo;
    out[(size_t)(r0 + 2) * 128 + o] = a2 + bo;
    out[(size_t)(r0 + 3) * 128 + o] = a3 + bo;
}

__global__ void fc2_kernel(const float* __restrict__ in, const float* __restrict__ w,
                           const float* __restrict__ b, float* __restrict__ out)
{
    const int idx = blockIdx.x * 256 + threadIdx.x;
    if (idx >= 10240) return;
    const int r = idx / 10, o = idx % 10;
    const float4* ir = (const float4*)(in + (size_t)r * 128);
    const float4* wr = (const float4*)(w + (size_t)o * 128);
    float a = 0.f;
#pragma unroll
    for (int f = 0; f < 32; f++) {
        float4 x = ir[f], wv = wr[f];
        a = fmaf(x.x, wv.x, fmaf(x.y, wv.y, fmaf(x.z, wv.z, fmaf(x.w, wv.w, a))));
    }
    out[idx] = a + b[o];
}

__global__ void lif_kernel(const float* __restrict__ y, float* __restrict__ s, int sites)
{
    const int idx = blockIdx.x * 256 + threadIdx.x;
    if (idx >= sites) return;
    float v = 0.f;
#pragma unroll
    for (int t = 0; t < TSTEPS; t++) {
        float x = y[(size_t)t * sites + idx];
        v = v + (x - v) * 0.5f;
        float spike = (v >= 1.0f) ? 1.0f : 0.0f;
        s[(size_t)t * sites + idx] = spike;
        if (v >= 1.0f) v = 0.0f;
    }
}

__global__ void lif_mean_kernel(const float* __restrict__ y, float* __restrict__ out,
                                int sites)
{
    const int idx = blockIdx.x * 256 + threadIdx.x;
    if (idx >= sites) return;
    float v = 0.f, cnt = 0.f;
#pragma unroll
    for (int t = 0; t < TSTEPS; t++) {
        float x = y[(size_t)t * sites + idx];
        v = v + (x - v) * 0.5f;
        if (v >= 1.0f) { cnt += 1.0f; v = 0.0f; }
    }
    out[idx] = cnt * 0.125f;
}

// ---------------------------------------------------------------------------
extern "C" void kernel_launch(void* const* d_in, const int* in_sizes, int n_in,
                              void* d_out, int out_size)
{
    const float* x = (const float*)d_in[0];
    const float* w[7];  const float* bb[7];  const float* gg[7];  const float* be[7];
    for (int L = 1; L <= 6; L++) {
        w [L] = (const float*)d_in[1 + 4 * (L - 1) + 0];
        bb[L] = (const float*)d_in[1 + 4 * (L - 1) + 1];
        gg[L] = (const float*)d_in[1 + 4 * (L - 1) + 2];
        be[L] = (const float*)d_in[1 + 4 * (L - 1) + 3];
    }
    const float* fc1_w = (const float*)d_in[25];
    const float* fc1_b = (const float*)d_in[26];
    const float* fc2_w = (const float*)d_in[27];
    const float* fc2_b = (const float*)d_in[28];
    float* out = (float*)d_out;

    float *y, *s, *sp, *f1, *f1s, *f2;
    cudaGetSymbolAddress((void**)&y,   g_y);
    cudaGetSymbolAddress((void**)&s,   g_s);
    cudaGetSymbolAddress((void**)&sp,  g_sp);
    cudaGetSymbolAddress((void**)&f1,  g_fc1);
    cudaGetSymbolAddress((void**)&f1s, g_fc1s);
    cudaGetSymbolAddress((void**)&f2,  g_fc2);

    // ---- Layer 1 ----
    conv3x3_kernel<3, 32, 32, 32, 1, 3><<<dim3(128, 4), 256>>>(x, w[1], bb[1], y);
    bn_stats_kernel<<<dim3(32, 64), 256>>>(y, 32, 256, 128);
    bn_finalize_kernel<<<1, 128>>>(gg[1], be[1], 32, 128.0 * 1024.0);
    bn_lif_kernel<<<16384, 256>>>(y, s, 32, 1024, 0);

    // ---- Layer 2 (+pool) ----
    conv3x3_kernel<32, 32, 32, 32, 1, 8><<<dim3(1024, 4), 256>>>(s, w[2], bb[2], y);
    bn_stats_kernel<<<dim3(32, 64), 256>>>(y, 32, 256, 1024);
    bn_finalize_kernel<<<1, 128>>>(gg[2], be[2], 32, 1024.0 * 1024.0);
    bn_lif_pool_kernel<<<4096, 256>>>(y, sp, 32, 32, 32);

    // ---- Layer 3 ----
    conv3x3_kernel<32, 64, 16, 16, 4, 8><<<dim3(256, 8), 256>>>(sp, w[3], bb[3], y);
    bn_stats_kernel<<<dim3(64, 64), 256>>>(y, 64, 64, 1024);
    bn_finalize_kernel<<<1, 128>>>(gg[3], be[3], 64, 1024.0 * 256.0);
    bn_lif_kernel<<<8192, 256>>>(y, s, 64, 256, (long)128 * 64 * 256);

    // ---- Layer 4 (+pool) ----
    conv3x3_kernel<64, 64, 16, 16, 4, 8><<<dim3(256, 8), 256>>>(s, w[4], bb[4], y);
    bn_stats_kernel<<<dim3(64, 64), 256>>>(y, 64, 64, 1024);
    bn_finalize_kernel<<<1, 128>>>(gg[4], be[4], 64, 1024.0 * 256.0);
    bn_lif_pool_kernel<<<2048, 256>>>(y, sp, 64, 16, 16);

    // ---- Layer 5 ----
    conv3x3_kernel<64, 128, 8, 8, 16, 4><<<dim3(64, 16), 256>>>(sp, w[5], bb[5], y);
    bn_stats_kernel<<<dim3(128, 64), 256>>>(y, 128, 16, 1024);
    bn_finalize_kernel<<<1, 128>>>(gg[5], be[5], 128, 1024.0 * 64.0);
    bn_lif_kernel<<<4096, 256>>>(y, s, 128, 64, (long)128 * 128 * 64);

    // ---- Layer 6 (+pool) ----
    conv3x3_kernel<128, 128, 8, 8, 16, 4><<<dim3(64, 16), 256>>>(s, w[6], bb[6], y);
    bn_stats_kernel<<<dim3(128, 64), 256>>>(y, 128, 16, 1024);
    bn_finalize_kernel<<<1, 128>>>(gg[6], be[6], 128, 1024.0 * 64.0);
    bn_lif_pool_kernel<<<1024, 256>>>(y, sp, 128, 8, 8);

    // ---- FC head ----
    fc1_kernel<<<256, 128>>>(sp, fc1_w, fc1_b, f1);
    lif_kernel<<<64, 256>>>(f1, f1s, 16384);
    fc2_kernel<<<40, 256>>>(f1s, fc2_w, fc2_b, f2);
    lif_mean_kernel<<<5, 256>>>(f2, out, 1280);
}